// round 1
// baseline (speedup 1.0000x reference)
#include <cuda_runtime.h>

#define NCFG 128
#define VEC  16384
#define NB   8192
#define ETA  0.001f

// Scratch (no allocation allowed): per-config vec (bot||top) and NN hidden layer.
__device__ float g_vec[NCFG * VEC];   // 8 MB
__device__ float g_h[NCFG * 64];

// ---------------------------------------------------------------------------
// Kernel 1: per-config base tensors + eta*b2, and h = relu(cfg @ W1 + b1)
// A layout: (8,4,4,4,4,4,2) C-contiguous: A[x,y,a,b,c,d,p]
// s[x,y,q] = A[(xy*256+q)*2 + p(x,y)],  q = a*64+b*16+c*4+d
// bot[x,(l,L),(r,R),U] = sum_u s[x,0,l,r,0,u] * s[x,1,L,R,u,U]
// top[x,(l,L),(r,R),d] = sum_u s[x,2,l,r,d,u] * s[x,3,L,R,u,0]
// ---------------------------------------------------------------------------
__global__ void k_base(const int* __restrict__ cfg,
                       const float* __restrict__ A,
                       const float* __restrict__ W1,
                       const float* __restrict__ b1,
                       const float* __restrict__ b2)
{
    __shared__ float s[8192];   // 8 sites x 4 rows x 256
    __shared__ int   p[32];
    const int b   = blockIdx.x;
    const int tid = threadIdx.x;   // 256 threads

    if (tid < 32) p[tid] = cfg[b * 32 + tid];
    __syncthreads();

    // Gather phys-selected slices of A into smem
    for (int n = tid; n < 8192; n += 256) {
        int xy = n >> 8;            // x*4 + y
        int q  = n & 255;
        s[n] = A[(xy * 256 + q) * 2 + p[xy]];
    }
    __syncthreads();

    float* vout = g_vec + b * VEC;
    for (int n = tid; n < VEC; n += 256) {
        float acc = 0.f;
        if (n < NB) {
            int x   = n >> 10;
            int rem = n & 1023;
            int i = rem >> 6, j = (rem >> 2) & 15, U = rem & 3;
            int l = i >> 2, L = i & 3, r = j >> 2, R = j & 3;
            const float* s0 = s + (x * 4 + 0) * 256;
            const float* s1 = s + (x * 4 + 1) * 256;
            #pragma unroll
            for (int u = 0; u < 4; u++)
                acc = fmaf(s0[l * 64 + r * 16 + u], s1[L * 64 + R * 16 + u * 4 + U], acc);
        } else {
            int m   = n - NB;
            int x   = m >> 10;
            int rem = m & 1023;
            int i = rem >> 6, j = (rem >> 2) & 15, d = rem & 3;
            int l = i >> 2, L = i & 3, r = j >> 2, R = j & 3;
            const float* s2 = s + (x * 4 + 2) * 256;
            const float* s3 = s + (x * 4 + 3) * 256;
            #pragma unroll
            for (int u = 0; u < 4; u++)
                acc = fmaf(s2[l * 64 + r * 16 + d * 4 + u], s3[L * 64 + R * 16 + u * 4], acc);
        }
        vout[n] = acc + ETA * b2[n];
    }

    // h = relu(cfg_f @ W1 + b1)   (cfg entries are 0/1)
    if (tid < 64) {
        float acc = b1[tid];
        #pragma unroll
        for (int i = 0; i < 32; i++)
            acc = fmaf((float)p[i], W1[i * 64 + tid], acc);
        g_h[b * 64 + tid] = fmaxf(acc, 0.f);
    }
}

// ---------------------------------------------------------------------------
// Kernel 2: g_vec += ETA * (H @ W2)
// H: 128x64 (all configs), W2: 64x16384. Each block: 128 rows x 32 cols.
// 256 threads = 32 row-groups x 8 col-groups, 4x4 register microtile.
// W2 is read exactly once across the grid.
// ---------------------------------------------------------------------------
__global__ void k_gemm(const float* __restrict__ W2)
{
    __shared__ float sH[128][65];   // padded vs 4-way bank conflict
    __shared__ float sW[64][32];
    const int tid     = threadIdx.x;          // 256
    const int colBase = blockIdx.x * 32;      // 512 blocks

    for (int n = tid; n < 8192; n += 256)
        sH[n >> 6][n & 63] = g_h[n];
    for (int n = tid; n < 2048; n += 256)
        sW[n >> 5][n & 31] = W2[(n >> 5) * 16384 + colBase + (n & 31)];
    __syncthreads();

    const int tx = tid & 7;    // col group (4 cols)
    const int ry = tid >> 3;   // row group (4 rows)

    float acc[4][4] = {};
    #pragma unroll 8
    for (int k = 0; k < 64; k++) {
        float a0 = sH[ry * 4 + 0][k];
        float a1 = sH[ry * 4 + 1][k];
        float a2 = sH[ry * 4 + 2][k];
        float a3 = sH[ry * 4 + 3][k];
        float w0 = sW[k][tx * 4 + 0];
        float w1 = sW[k][tx * 4 + 1];
        float w2 = sW[k][tx * 4 + 2];
        float w3 = sW[k][tx * 4 + 3];
        acc[0][0] = fmaf(a0, w0, acc[0][0]); acc[0][1] = fmaf(a0, w1, acc[0][1]);
        acc[0][2] = fmaf(a0, w2, acc[0][2]); acc[0][3] = fmaf(a0, w3, acc[0][3]);
        acc[1][0] = fmaf(a1, w0, acc[1][0]); acc[1][1] = fmaf(a1, w1, acc[1][1]);
        acc[1][2] = fmaf(a1, w2, acc[1][2]); acc[1][3] = fmaf(a1, w3, acc[1][3]);
        acc[2][0] = fmaf(a2, w0, acc[2][0]); acc[2][1] = fmaf(a2, w1, acc[2][1]);
        acc[2][2] = fmaf(a2, w2, acc[2][2]); acc[2][3] = fmaf(a2, w3, acc[2][3]);
        acc[3][0] = fmaf(a3, w0, acc[3][0]); acc[3][1] = fmaf(a3, w1, acc[3][1]);
        acc[3][2] = fmaf(a3, w2, acc[3][2]); acc[3][3] = fmaf(a3, w3, acc[3][3]);
    }

    #pragma unroll
    for (int i = 0; i < 4; i++) {
        int row = ry * 4 + i;
        #pragma unroll
        for (int j = 0; j < 4; j++) {
            int col = colBase + tx * 4 + j;
            g_vec[row * VEC + col] += ETA * acc[i][j];
        }
    }
}

// ---------------------------------------------------------------------------
// Kernel 3: factored transfer-matrix chain, never materializing M.
// vmat(16x16) starts as e0. Per step x:
//   T[i,J,u]   = sum_I vmat[i,I] * top2[x,I,J,u]
//   v'[j,J]    = sum_{i,u} bot2[x,i,j,u] * T[i,J,u]
// out[b] = vmat[0,0] after 8 steps.
// ---------------------------------------------------------------------------
__global__ void k_chain(float* __restrict__ out)
{
    __shared__ float sbot[1024], stop[1024];
    __shared__ float vmat[256], T[1024], vnew[256];
    const int b   = blockIdx.x;
    const int tid = threadIdx.x;   // 128
    const float* vb = g_vec + b * VEC;

    for (int n = tid; n < 256; n += 128) vmat[n] = (n == 0) ? 1.f : 0.f;

    for (int x = 0; x < 8; x++) {
        __syncthreads();
        for (int n = tid; n < 1024; n += 128) {
            sbot[n] = vb[x * 1024 + n];
            stop[n] = vb[NB + x * 1024 + n];
        }
        __syncthreads();
        // T[i*64 + J*4 + u]
        for (int t = tid; t < 1024; t += 128) {
            int i = t >> 6, Ju = t & 63;
            float acc = 0.f;
            #pragma unroll
            for (int I = 0; I < 16; I++)
                acc = fmaf(vmat[i * 16 + I], stop[I * 64 + Ju], acc);
            T[t] = acc;
        }
        __syncthreads();
        // vnew[j*16 + J]
        for (int t = tid; t < 256; t += 128) {
            int j = t >> 4, J = t & 15;
            float acc = 0.f;
            #pragma unroll
            for (int i = 0; i < 16; i++)
                #pragma unroll
                for (int u = 0; u < 4; u++)
                    acc = fmaf(sbot[i * 64 + j * 4 + u], T[i * 64 + J * 4 + u], acc);
            vnew[t] = acc;
        }
        __syncthreads();
        for (int n = tid; n < 256; n += 128) vmat[n] = vnew[n];
    }
    __syncthreads();
    if (tid == 0) out[b] = vmat[0];
}

// ---------------------------------------------------------------------------
extern "C" void kernel_launch(void* const* d_in, const int* in_sizes, int n_in,
                              void* d_out, int out_size)
{
    const int*   cfg = (const int*)  d_in[0];
    const float* A   = (const float*)d_in[1];
    const float* W1  = (const float*)d_in[2];
    const float* b1  = (const float*)d_in[3];
    const float* W2  = (const float*)d_in[4];
    const float* b2  = (const float*)d_in[5];
    float* out = (float*)d_out;

    k_base <<<128, 256>>>(cfg, A, W1, b1, b2);
    k_gemm <<<512, 256>>>(W2);
    k_chain<<<128, 128>>>(out);
}

// round 4
// speedup vs baseline: 1.6242x; 1.6242x over previous
#include <cuda_runtime.h>

#define NCFG 128
#define VEC  16384
#define NB   8192
#define ETA  0.001f

// Scratch (no allocation allowed)
__device__ float g_vec[NCFG * VEC];   // 8 MB: per-config (bot || top)
__device__ float g_h[NCFG * 64];      // NN hidden layer

// ---------------------------------------------------------------------------
// Kernel 1: per-(config, x-site) base tensors + eta*b2; h for x==0 blocks.
// grid = 128 cfg * 8 x = 1024 blocks, 256 threads.
// A layout (8,4,4,4,4,4,2): A[x,y,a,b,c,d,p]; q = a*64+b*16+c*4+d.
// bot[x,(l,L),(r,R),U] = sum_u s[x,0,l,r,0,u] * s[x,1,L,R,u,U]
// top[x,(l,L),(r,R),d] = sum_u s[x,2,l,r,d,u] * s[x,3,L,R,u,0]
// ---------------------------------------------------------------------------
__global__ void k_base(const int* __restrict__ cfg,
                       const float* __restrict__ A,
                       const float* __restrict__ W1,
                       const float* __restrict__ b1,
                       const float* __restrict__ b2)
{
    __shared__ float s[4][256];
    __shared__ int   p[4];
    const int blk = blockIdx.x;
    const int b   = blk >> 3;
    const int x   = blk & 7;
    const int tid = threadIdx.x;   // 256

    if (tid < 4) p[tid] = cfg[b * 32 + x * 4 + tid];
    __syncthreads();

    // Gather phys-selected slices: coalesced float2 loads + select
    #pragma unroll
    for (int t = 0; t < 4; t++) {
        int n = tid + t * 256;     // 0..1023
        int y = n >> 8, q = n & 255;
        float2 a2 = ((const float2*)A)[(x * 4 + y) * 256 + q];
        s[y][q] = p[y] ? a2.y : a2.x;
    }
    __syncthreads();

    float* vout = g_vec + b * VEC;

    // bot slice: 1024 outputs
    #pragma unroll
    for (int t = 0; t < 4; t++) {
        int n = tid + t * 256;
        int i = n >> 6, j = (n >> 2) & 15, U = n & 3;
        int l = i >> 2, L = i & 3, r = j >> 2, R = j & 3;
        float acc = 0.f;
        #pragma unroll
        for (int u = 0; u < 4; u++)
            acc = fmaf(s[0][l * 64 + r * 16 + u], s[1][L * 64 + R * 16 + u * 4 + U], acc);
        vout[x * 1024 + n] = acc + ETA * b2[x * 1024 + n];
    }

    // top slice: 1024 outputs
    #pragma unroll
    for (int t = 0; t < 4; t++) {
        int n = tid + t * 256;
        int i = n >> 6, j = (n >> 2) & 15, d = n & 3;
        int l = i >> 2, L = i & 3, r = j >> 2, R = j & 3;
        float acc = 0.f;
        #pragma unroll
        for (int u = 0; u < 4; u++)
            acc = fmaf(s[2][l * 64 + r * 16 + d * 4 + u], s[3][L * 64 + R * 16 + u * 4], acc);
        vout[NB + x * 1024 + n] = acc + ETA * b2[NB + x * 1024 + n];
    }

    // h = relu(cfg_f @ W1 + b1), computed by x==0 blocks
    if (x == 0 && tid < 64) {
        float acc = b1[tid];
        #pragma unroll
        for (int i = 0; i < 32; i++)
            acc = fmaf((float)cfg[b * 32 + i], W1[i * 64 + tid], acc);
        g_h[b * 64 + tid] = fmaxf(acc, 0.f);
    }
}

// ---------------------------------------------------------------------------
// Kernel 2: g_vec += ETA * (H @ W2) using packed fma.rn.f32x2 (FFMA2).
// H: 128x64, W2: 64x16384. Block: 128 rows x 64 cols; 256 blocks.
// Thread microtile: 8 rows (4 row-pairs in f32x2 lanes) x 4 cols.
// W2 is read exactly once across the grid.
// ---------------------------------------------------------------------------
__global__ void k_gemm(const float* __restrict__ W2)
{
    __shared__ float sHT[64][130];  // H transposed [k][row], padded (stride%32==2, 8B-aligned pairs)
    __shared__ float sW[64][64];    // W tile [k][col]
    const int tid     = threadIdx.x;          // 256
    const int colBase = blockIdx.x * 64;      // 256 blocks

    for (int n = tid; n < 8192; n += 256) {
        int r = n >> 6, k = n & 63;
        sHT[k][r] = g_h[n];
    }
    for (int n = tid; n < 4096; n += 256) {
        int k = n >> 6, c = n & 63;
        sW[k][c] = W2[k * 16384 + colBase + c];
    }
    __syncthreads();

    const int rb = tid >> 4;   // 0..15 -> rows rb*8 .. rb*8+7
    const int cb = tid & 15;   // 0..15 -> cols cb*4 .. cb*4+3

    unsigned long long acc[4][4];  // [row-pair][col], lanes = (row 2p, row 2p+1)
    #pragma unroll
    for (int p = 0; p < 4; p++)
        #pragma unroll
        for (int j = 0; j < 4; j++) acc[p][j] = 0ull;

    #pragma unroll 8
    for (int k = 0; k < 64; k++) {
        unsigned long long a[4], w[4];
        #pragma unroll
        for (int p = 0; p < 4; p++)
            a[p] = *(const unsigned long long*)&sHT[k][rb * 8 + 2 * p];
        #pragma unroll
        for (int j = 0; j < 4; j++) {
            float wv = sW[k][cb * 4 + j];
            asm("mov.b64 %0, {%1, %2};" : "=l"(w[j]) : "f"(wv), "f"(wv));
        }
        #pragma unroll
        for (int p = 0; p < 4; p++)
            #pragma unroll
            for (int j = 0; j < 4; j++)
                asm("fma.rn.f32x2 %0, %1, %2, %0;"
                    : "+l"(acc[p][j]) : "l"(a[p]), "l"(w[j]));
    }

    #pragma unroll
    for (int p = 0; p < 4; p++) {
        int r0 = rb * 8 + 2 * p;
        #pragma unroll
        for (int j = 0; j < 4; j++) {
            float2 v = *(float2*)&acc[p][j];
            int col = colBase + cb * 4 + j;
            g_vec[(unsigned)(r0    ) * VEC + col] += ETA * v.x;
            g_vec[(unsigned)(r0 + 1) * VEC + col] += ETA * v.y;
        }
    }
}

// ---------------------------------------------------------------------------
// Kernel 3: factored transfer-matrix chain (M never materialized).
// vmat(16x16) starts as e0. Per step x:
//   T[i,J,u] = sum_I vmat[i,I] * top2[x,I,J,u]
//   v'[j,J]  = sum_{i,u} bot2[x,i,j,u] * T[i,J,u]
// out[b] = vmat[0,0] after 8 steps.
// ---------------------------------------------------------------------------
__global__ void k_chain(float* __restrict__ out)
{
    __shared__ float sbot[1024], stop[1024];
    __shared__ float vmat[256], T[1024], vnew[256];
    const int b   = blockIdx.x;
    const int tid = threadIdx.x;   // 256
    const float* vb = g_vec + b * VEC;

    if (tid < 256) vmat[tid] = (tid == 0) ? 1.f : 0.f;

    for (int x = 0; x < 8; x++) {
        __syncthreads();
        #pragma unroll
        for (int t = 0; t < 4; t++) {
            int n = tid + t * 256;
            sbot[n] = vb[x * 1024 + n];
            stop[n] = vb[NB + x * 1024 + n];
        }
        __syncthreads();
        // T[i*64 + J*4 + u]
        #pragma unroll
        for (int t = 0; t < 4; t++) {
            int n = tid + t * 256;
            int i = n >> 6, Ju = n & 63;
            float acc = 0.f;
            #pragma unroll
            for (int I = 0; I < 16; I++)
                acc = fmaf(vmat[i * 16 + I], stop[I * 64 + Ju], acc);
            T[n] = acc;
        }
        __syncthreads();
        // vnew[j*16 + J]
        {
            int j = tid >> 4, J = tid & 15;
            float acc = 0.f;
            #pragma unroll
            for (int i = 0; i < 16; i++)
                #pragma unroll
                for (int u = 0; u < 4; u++)
                    acc = fmaf(sbot[i * 64 + j * 4 + u], T[i * 64 + J * 4 + u], acc);
            vnew[tid] = acc;
        }
        __syncthreads();
        vmat[tid] = vnew[tid];
    }
    __syncthreads();
    if (tid == 0) out[b] = vmat[0];
}

// ---------------------------------------------------------------------------
extern "C" void kernel_launch(void* const* d_in, const int* in_sizes, int n_in,
                              void* d_out, int out_size)
{
    const int*   cfg = (const int*)  d_in[0];
    const float* A   = (const float*)d_in[1];
    const float* W1  = (const float*)d_in[2];
    const float* b1  = (const float*)d_in[3];
    const float* W2  = (const float*)d_in[4];
    const float* b2  = (const float*)d_in[5];
    float* out = (float*)d_out;

    k_base <<<1024, 256>>>(cfg, A, W1, b1, b2);
    k_gemm <<<256, 256>>>(W2);
    k_chain<<<128, 256>>>(out);
}

// round 5
// speedup vs baseline: 1.7008x; 1.0471x over previous
#include <cuda_runtime.h>

#define NCFG 128
#define VEC  16384
#define NB   8192
#define ETA  0.001f

// Scratch (no allocation allowed)
__device__ float g_vec[NCFG * VEC];   // 8 MB: per-config (bot || top)
__device__ float g_h[NCFG * 64];      // NN hidden layer

// ---------------------------------------------------------------------------
// Kernel 1: per-(config, x-site) base tensors + eta*b2; h for x==0 blocks.
// grid = 1024 (128 cfg x 8 x), 256 threads. Each thread emits one float4 of
// bot (U=0..3) and one float4 of top (d=0..3).
// ---------------------------------------------------------------------------
__global__ void k_base(const int* __restrict__ cfg,
                       const float* __restrict__ A,
                       const float* __restrict__ W1,
                       const float* __restrict__ b1,
                       const float* __restrict__ b2)
{
    __shared__ float s[4][256];
    __shared__ int   p[4];
    const int blk = blockIdx.x;
    const int b   = blk >> 3;
    const int x   = blk & 7;
    const int tid = threadIdx.x;   // 256

    if (tid < 4) p[tid] = cfg[b * 32 + x * 4 + tid];
    __syncthreads();

    #pragma unroll
    for (int t = 0; t < 4; t++) {
        int n = tid + t * 256;
        int y = n >> 8, q = n & 255;
        float2 a2 = ((const float2*)A)[(x * 4 + y) * 256 + q];
        s[y][q] = p[y] ? a2.y : a2.x;
    }
    __syncthreads();

    float* vout = g_vec + b * VEC;
    const int n0 = tid * 4;                 // quad base: i,j fixed, last idx 0..3
    const int i = n0 >> 6, j = (n0 >> 2) & 15;
    const int l = i >> 2, L = i & 3, r = j >> 2, R = j & 3;

    // bot quad: bot[i,j,U] = sum_u s0[l,r,u] * s1[L,R,u*4+U]
    {
        float4 acc = make_float4(0.f, 0.f, 0.f, 0.f);
        #pragma unroll
        for (int u = 0; u < 4; u++) {
            float a = s[0][l * 64 + r * 16 + u];
            float4 w = *(const float4*)&s[1][L * 64 + R * 16 + u * 4];
            acc.x = fmaf(a, w.x, acc.x); acc.y = fmaf(a, w.y, acc.y);
            acc.z = fmaf(a, w.z, acc.z); acc.w = fmaf(a, w.w, acc.w);
        }
        float4 bb = *(const float4*)&b2[x * 1024 + n0];
        acc.x = fmaf(ETA, bb.x, acc.x); acc.y = fmaf(ETA, bb.y, acc.y);
        acc.z = fmaf(ETA, bb.z, acc.z); acc.w = fmaf(ETA, bb.w, acc.w);
        *(float4*)&vout[x * 1024 + n0] = acc;
    }

    // top quad: top[i,j,d] = sum_u s2[l,r,d*4+u] * s3[L,R,u*4]
    {
        float w0 = s[3][L * 64 + R * 16 + 0];
        float w1 = s[3][L * 64 + R * 16 + 4];
        float w2 = s[3][L * 64 + R * 16 + 8];
        float w3 = s[3][L * 64 + R * 16 + 12];
        float4 acc;
        #pragma unroll
        for (int d = 0; d < 4; d++) {
            float4 v = *(const float4*)&s[2][l * 64 + r * 16 + d * 4];
            float a = fmaf(v.x, w0, fmaf(v.y, w1, fmaf(v.z, w2, v.w * w3)));
            ((float*)&acc)[d] = a;
        }
        float4 bb = *(const float4*)&b2[NB + x * 1024 + n0];
        acc.x = fmaf(ETA, bb.x, acc.x); acc.y = fmaf(ETA, bb.y, acc.y);
        acc.z = fmaf(ETA, bb.z, acc.z); acc.w = fmaf(ETA, bb.w, acc.w);
        *(float4*)&vout[NB + x * 1024 + n0] = acc;
    }

    // h = relu(cfg_f @ W1 + b1)
    if (x == 0 && tid < 64) {
        float acc = b1[tid];
        #pragma unroll
        for (int ii = 0; ii < 32; ii++)
            acc = fmaf((float)cfg[b * 32 + ii], W1[ii * 64 + tid], acc);
        g_h[b * 64 + tid] = fmaxf(acc, 0.f);
    }
}

// ---------------------------------------------------------------------------
// Kernel 2: g_vec += ETA * (H @ W2) with fma.rn.f32x2, COLUMN-pair packing.
// H: 128x64, W2: 64x16384. Block: 128 rows x 64 cols; 256 blocks.
// Thread microtile: 4 rows x 8 cols (4 col-pairs in f32x2 lanes).
// W loads = conflict-free LDS.64; epilogue = coalesced float2 RMW.
// ---------------------------------------------------------------------------
__global__ void k_gemm(const float* __restrict__ W2)
{
    __shared__ float sH[128][65];   // [row][k], padded
    __shared__ float sW[64][64];    // [k][col]
    const int tid     = threadIdx.x;          // 256
    const int colBase = blockIdx.x * 64;      // 256 blocks

    for (int n = tid; n < 8192; n += 256)
        sH[n >> 6][n & 63] = g_h[n];
    for (int n = tid; n < 4096; n += 256)
        sW[n >> 6][n & 63] = W2[(n >> 6) * 16384 + colBase + (n & 63)];
    __syncthreads();

    const int rb = tid >> 3;   // 0..31 -> rows rb*4 .. rb*4+3
    const int cb = tid & 7;    // 0..7  -> cols cb*8 .. cb*8+7 (4 pairs)

    unsigned long long acc[4][4];  // [row][col-pair], lanes = (col 2j, col 2j+1)
    #pragma unroll
    for (int i = 0; i < 4; i++)
        #pragma unroll
        for (int j = 0; j < 4; j++) acc[i][j] = 0ull;

    #pragma unroll 8
    for (int k = 0; k < 64; k++) {
        unsigned long long h[4], w[4];
        #pragma unroll
        for (int i = 0; i < 4; i++) {
            float hv = sH[rb * 4 + i][k];
            asm("mov.b64 %0, {%1, %2};" : "=l"(h[i]) : "f"(hv), "f"(hv));
        }
        #pragma unroll
        for (int j = 0; j < 4; j++)
            w[j] = *(const unsigned long long*)&sW[k][cb * 8 + 2 * j];
        #pragma unroll
        for (int i = 0; i < 4; i++)
            #pragma unroll
            for (int j = 0; j < 4; j++)
                asm("fma.rn.f32x2 %0, %1, %2, %0;"
                    : "+l"(acc[i][j]) : "l"(h[i]), "l"(w[j]));
    }

    #pragma unroll
    for (int i = 0; i < 4; i++) {
        unsigned row = rb * 4 + i;
        #pragma unroll
        for (int j = 0; j < 4; j++) {
            float2* dst = (float2*)&g_vec[row * VEC + colBase + cb * 8 + 2 * j];
            float2 old = *dst;
            float2 v = *(float2*)&acc[i][j];
            old.x = fmaf(ETA, v.x, old.x);
            old.y = fmaf(ETA, v.y, old.y);
            *dst = old;
        }
    }
}

// ---------------------------------------------------------------------------
// Kernel 3: factored transfer-matrix chain with register prefetch +
// ping-pong vmat. 128 blocks (one per config), 256 threads.
//   T[i,J,u] = sum_I vmat[i,I] * top2[x,I,J,u]
//   v'[j,J]  = sum_{i,u} bot2[x,i,j,u] * T[i,J,u]
// ---------------------------------------------------------------------------
__global__ void k_chain(float* __restrict__ out)
{
    __shared__ float sbot[1024], stop[1024];
    __shared__ float T[1024];
    __shared__ float vbuf[2][256];
    const int b   = blockIdx.x;
    const int tid = threadIdx.x;   // 256
    const float* vb = g_vec + b * VEC;

    vbuf[0][tid] = (tid == 0) ? 1.f : 0.f;

    // prefetch step 0
    float4 pb = *(const float4*)&vb[tid * 4];
    float4 pt = *(const float4*)&vb[NB + tid * 4];

    int cur = 0;
    for (int x = 0; x < 8; x++) {
        __syncthreads();   // prev step's smem reads done; vbuf[cur] ready
        *(float4*)&sbot[tid * 4] = pb;
        *(float4*)&stop[tid * 4] = pt;
        __syncthreads();

        if (x < 7) {       // prefetch next step (overlaps with compute below)
            pb = *(const float4*)&vb[(x + 1) * 1024 + tid * 4];
            pt = *(const float4*)&vb[NB + (x + 1) * 1024 + tid * 4];
        }

        // T quad: n0 = tid*4 -> i,J fixed, u = 0..3
        {
            const int n0 = tid * 4;
            const int i = n0 >> 6, J = (n0 >> 2) & 15;
            float4 acc = make_float4(0.f, 0.f, 0.f, 0.f);
            #pragma unroll
            for (int I = 0; I < 16; I++) {
                float vv = vbuf[cur][i * 16 + I];
                float4 tp = *(const float4*)&stop[I * 64 + J * 4];
                acc.x = fmaf(vv, tp.x, acc.x); acc.y = fmaf(vv, tp.y, acc.y);
                acc.z = fmaf(vv, tp.z, acc.z); acc.w = fmaf(vv, tp.w, acc.w);
            }
            *(float4*)&T[n0] = acc;
        }
        __syncthreads();

        // vnew[j*16+J]
        {
            const int j = tid >> 4, J = tid & 15;
            float acc = 0.f;
            #pragma unroll
            for (int i = 0; i < 16; i++) {
                float4 bo = *(const float4*)&sbot[i * 64 + j * 4];
                float4 tt = *(const float4*)&T[i * 64 + J * 4];
                acc = fmaf(bo.x, tt.x, acc);
                acc = fmaf(bo.y, tt.y, acc);
                acc = fmaf(bo.z, tt.z, acc);
                acc = fmaf(bo.w, tt.w, acc);
            }
            vbuf[cur ^ 1][tid] = acc;
        }
        cur ^= 1;
    }
    __syncthreads();
    if (tid == 0) out[b] = vbuf[cur][0];
}

// ---------------------------------------------------------------------------
extern "C" void kernel_launch(void* const* d_in, const int* in_sizes, int n_in,
                              void* d_out, int out_size)
{
    const int*   cfg = (const int*)  d_in[0];
    const float* A   = (const float*)d_in[1];
    const float* W1  = (const float*)d_in[2];
    const float* b1  = (const float*)d_in[3];
    const float* W2  = (const float*)d_in[4];
    const float* b2  = (const float*)d_in[5];
    float* out = (float*)d_out;

    k_base <<<1024, 256>>>(cfg, A, W1, b1, b2);
    k_gemm <<<256, 256>>>(W2);
    k_chain<<<128, 256>>>(out);
}

// round 6
// speedup vs baseline: 1.9241x; 1.1313x over previous
#include <cuda_runtime.h>

#define NCFG 128
#define VEC  16384
#define NB   8192
#define ETA  0.001f
#define NBLK 256

// Scratch (no allocation allowed)
__device__ float g_vec[NCFG * VEC];   // 8 MB: per-config (bot || top)
__device__ float g_h[NCFG * 64];      // NN hidden layer
__device__ unsigned g_cnt   = 0;      // grid barrier arrivals
__device__ unsigned g_epoch = 0;      // grid barrier generation (monotonic)

union Smem {
    struct { float s[4][256]; int p[4]; } p1;
    struct { float sH[128][66]; float sW[64][32]; } p2;             // 41984 B
    struct { float sbot[1024], stop[1024], T[1024]; float vbuf[2][256]; } p3;
};

// Sense-free grid barrier: epoch is monotonic across graph replays; the count
// resets to 0 each pass (last arriver resets before bumping epoch).
// Safe because all NBLK blocks are co-resident (2 blocks/SM guaranteed by
// __launch_bounds__(256,2) + 42KB smem).
__device__ __forceinline__ void grid_barrier() {
    __syncthreads();
    if (threadIdx.x == 0) {
        __threadfence();
        volatile unsigned* ep = &g_epoch;
        unsigned base = *ep;                 // stable: no bump before all arrive
        unsigned old = atomicAdd(&g_cnt, 1);
        if (old == NBLK - 1) {
            g_cnt = 0;                       // reset for next barrier
            __threadfence();
            atomicAdd(&g_epoch, 1);          // release
        } else {
            while (*ep == base) __nanosleep(32);
        }
        __threadfence();
    }
    __syncthreads();
}

__global__ void __launch_bounds__(256, 2)
k_fused(const int* __restrict__ cfg,
        const float* __restrict__ A,
        const float* __restrict__ W1,
        const float* __restrict__ b1,
        const float* __restrict__ W2,
        const float* __restrict__ b2,
        float* __restrict__ out)
{
    __shared__ Smem sm;
    const int blk = blockIdx.x;
    const int tid = threadIdx.x;   // 256

    // ================= Phase 1: base tensors + eta*b2, and h =================
    // 1024 (config, x) tiles, 4 per block.
    #pragma unroll 1
    for (int ti = 0; ti < 4; ti++) {
        const int tile = blk * 4 + ti;
        const int b = tile >> 3, x = tile & 7;

        if (tid < 4) sm.p1.p[tid] = cfg[b * 32 + x * 4 + tid];
        __syncthreads();

        #pragma unroll
        for (int t = 0; t < 4; t++) {
            int n = tid + t * 256;
            int y = n >> 8, q = n & 255;
            float2 a2 = ((const float2*)A)[(x * 4 + y) * 256 + q];
            sm.p1.s[y][q] = sm.p1.p[y] ? a2.y : a2.x;
        }
        __syncthreads();

        float* vout = g_vec + b * VEC;
        const int n0 = tid * 4;
        const int i = n0 >> 6, j = (n0 >> 2) & 15;
        const int l = i >> 2, L = i & 3, r = j >> 2, R = j & 3;

        // bot quad: bot[i,j,U] = sum_u s0[l,r,u] * s1[L,R,u*4+U]
        {
            float4 acc = make_float4(0.f, 0.f, 0.f, 0.f);
            #pragma unroll
            for (int u = 0; u < 4; u++) {
                float a = sm.p1.s[0][l * 64 + r * 16 + u];
                float4 w = *(const float4*)&sm.p1.s[1][L * 64 + R * 16 + u * 4];
                acc.x = fmaf(a, w.x, acc.x); acc.y = fmaf(a, w.y, acc.y);
                acc.z = fmaf(a, w.z, acc.z); acc.w = fmaf(a, w.w, acc.w);
            }
            float4 bb = *(const float4*)&b2[x * 1024 + n0];
            acc.x = fmaf(ETA, bb.x, acc.x); acc.y = fmaf(ETA, bb.y, acc.y);
            acc.z = fmaf(ETA, bb.z, acc.z); acc.w = fmaf(ETA, bb.w, acc.w);
            *(float4*)&vout[x * 1024 + n0] = acc;
        }
        // top quad: top[i,j,d] = sum_u s2[l,r,d*4+u] * s3[L,R,u*4]
        {
            float w0 = sm.p1.s[3][L * 64 + R * 16 + 0];
            float w1 = sm.p1.s[3][L * 64 + R * 16 + 4];
            float w2 = sm.p1.s[3][L * 64 + R * 16 + 8];
            float w3 = sm.p1.s[3][L * 64 + R * 16 + 12];
            float4 acc;
            #pragma unroll
            for (int d = 0; d < 4; d++) {
                float4 v = *(const float4*)&sm.p1.s[2][l * 64 + r * 16 + d * 4];
                ((float*)&acc)[d] = fmaf(v.x, w0, fmaf(v.y, w1, fmaf(v.z, w2, v.w * w3)));
            }
            float4 bb = *(const float4*)&b2[NB + x * 1024 + n0];
            acc.x = fmaf(ETA, bb.x, acc.x); acc.y = fmaf(ETA, bb.y, acc.y);
            acc.z = fmaf(ETA, bb.z, acc.z); acc.w = fmaf(ETA, bb.w, acc.w);
            *(float4*)&vout[NB + x * 1024 + n0] = acc;
        }
        __syncthreads();
    }

    // h[blk] = relu(cfg[blk] @ W1 + b1), one config per block (blk < 128)
    if (blk < NCFG && tid < 64) {
        float acc = b1[tid];
        #pragma unroll
        for (int ii = 0; ii < 32; ii++)
            acc = fmaf((float)cfg[blk * 32 + ii], W1[ii * 64 + tid], acc);
        g_h[blk * 64 + tid] = fmaxf(acc, 0.f);
    }

    grid_barrier();

    // ================= Phase 2: g_vec += ETA * (H @ W2), FFMA2 ===============
    // 512 col-tiles of 32; each block does tiles blk and blk+256.
    for (int n = tid; n < 8192; n += 256)
        sm.p2.sH[n >> 6][n & 63] = g_h[n];      // [row][k], pad 66: conflict-free

    #pragma unroll 1
    for (int t = blk; t < 512; t += NBLK) {
        const int colBase = t * 32;
        __syncthreads();
        for (int n = tid; n < 2048; n += 256)
            sm.p2.sW[n >> 5][n & 31] = W2[(n >> 5) * 16384 + colBase + (n & 31)];
        __syncthreads();

        const int rb = tid >> 3;   // rows rb*4 .. rb*4+3
        const int cb = tid & 7;    // cols cb*4 .. cb*4+3 (2 f32x2 pairs)

        unsigned long long acc[4][2];
        #pragma unroll
        for (int i = 0; i < 4; i++) { acc[i][0] = 0ull; acc[i][1] = 0ull; }

        #pragma unroll 8
        for (int k = 0; k < 64; k++) {
            unsigned long long h[4], w[2];
            #pragma unroll
            for (int i = 0; i < 4; i++) {
                float hv = sm.p2.sH[rb * 4 + i][k];
                asm("mov.b64 %0, {%1, %2};" : "=l"(h[i]) : "f"(hv), "f"(hv));
            }
            w[0] = *(const unsigned long long*)&sm.p2.sW[k][cb * 4 + 0];
            w[1] = *(const unsigned long long*)&sm.p2.sW[k][cb * 4 + 2];
            #pragma unroll
            for (int i = 0; i < 4; i++) {
                asm("fma.rn.f32x2 %0, %1, %2, %0;" : "+l"(acc[i][0]) : "l"(h[i]), "l"(w[0]));
                asm("fma.rn.f32x2 %0, %1, %2, %0;" : "+l"(acc[i][1]) : "l"(h[i]), "l"(w[1]));
            }
        }

        #pragma unroll
        for (int i = 0; i < 4; i++) {
            unsigned row = rb * 4 + i;
            #pragma unroll
            for (int j = 0; j < 2; j++) {
                float2* dst = (float2*)&g_vec[row * VEC + colBase + cb * 4 + 2 * j];
                float2 old = *dst;
                float2 v = *(float2*)&acc[i][j];
                old.x = fmaf(ETA, v.x, old.x);
                old.y = fmaf(ETA, v.y, old.y);
                *dst = old;
            }
        }
    }

    grid_barrier();

    // ================= Phase 3: transfer-matrix chain (blk < 128) ============
    if (blk < NCFG) {
        const int b = blk;
        const float* vb = g_vec + b * VEC;

        sm.p3.vbuf[0][tid] = (tid == 0) ? 1.f : 0.f;

        float4 pb = *(const float4*)&vb[tid * 4];
        float4 pt = *(const float4*)&vb[NB + tid * 4];

        int cur = 0;
        #pragma unroll 1
        for (int x = 0; x < 8; x++) {
            __syncthreads();
            *(float4*)&sm.p3.sbot[tid * 4] = pb;
            *(float4*)&sm.p3.stop[tid * 4] = pt;
            __syncthreads();

            if (x < 7) {
                pb = *(const float4*)&vb[(x + 1) * 1024 + tid * 4];
                pt = *(const float4*)&vb[NB + (x + 1) * 1024 + tid * 4];
            }

            // T[i,J,u] quad
            {
                const int n0 = tid * 4;
                const int i = n0 >> 6, J = (n0 >> 2) & 15;
                float4 acc = make_float4(0.f, 0.f, 0.f, 0.f);
                #pragma unroll
                for (int I = 0; I < 16; I++) {
                    float vv = sm.p3.vbuf[cur][i * 16 + I];
                    float4 tp = *(const float4*)&sm.p3.stop[I * 64 + J * 4];
                    acc.x = fmaf(vv, tp.x, acc.x); acc.y = fmaf(vv, tp.y, acc.y);
                    acc.z = fmaf(vv, tp.z, acc.z); acc.w = fmaf(vv, tp.w, acc.w);
                }
                *(float4*)&sm.p3.T[n0] = acc;
            }
            __syncthreads();

            // vnew[j,J]
            {
                const int j = tid >> 4, J = tid & 15;
                float acc = 0.f;
                #pragma unroll
                for (int i = 0; i < 16; i++) {
                    float4 bo = *(const float4*)&sm.p3.sbot[i * 64 + j * 4];
                    float4 tt = *(const float4*)&sm.p3.T[i * 64 + J * 4];
                    acc = fmaf(bo.x, tt.x, acc);
                    acc = fmaf(bo.y, tt.y, acc);
                    acc = fmaf(bo.z, tt.z, acc);
                    acc = fmaf(bo.w, tt.w, acc);
                }
                sm.p3.vbuf[cur ^ 1][tid] = acc;
            }
            cur ^= 1;
        }
        __syncthreads();
        if (tid == 0) out[b] = sm.p3.vbuf[cur][0];
    }
}

// ---------------------------------------------------------------------------
extern "C" void kernel_launch(void* const* d_in, const int* in_sizes, int n_in,
                              void* d_out, int out_size)
{
    const int*   cfg = (const int*)  d_in[0];
    const float* A   = (const float*)d_in[1];
    const float* W1  = (const float*)d_in[2];
    const float* b1  = (const float*)d_in[3];
    const float* W2  = (const float*)d_in[4];
    const float* b2  = (const float*)d_in[5];
    float* out = (float*)d_out;

    k_fused<<<NBLK, 256>>>(cfg, A, W1, b1, W2, b2, out);
}